// round 1
// baseline (speedup 1.0000x reference)
#include <cuda_runtime.h>
#include <stdint.h>

// ============================================================================
// EnhancedAntiOverfittingAugmentation — fused single-kernel implementation.
// One CTA per sample. All stages (affine warp, hflip, color jitter w/ mean,
// 3x3 gaussian blur, random erasing, grid mask, clamp) operate on SMEM tiles.
// Randomness replicates JAX Threefry-2x32 with threefry_partitionable=True
// (modern JAX default): split(key,n)[j] = tf(key,0,j) (both lanes),
// random_bits32[i] = lane0 ^ lane1 of tf(key, 0, i).
// ============================================================================

#define NTHREADS 256
#define BATCH 2048
#define HWpx 4096
#define CHW 12288

__device__ __forceinline__ uint32_t rotl32(uint32_t v, int d) {
    return (v << d) | (v >> (32 - d));
}

// Threefry-2x32, 20 rounds, exactly as in jax._src.prng
__device__ __forceinline__ void tf2x32(uint32_t k0, uint32_t k1,
                                       uint32_t x0, uint32_t x1,
                                       uint32_t &o0, uint32_t &o1) {
    const uint32_t ks2 = k0 ^ k1 ^ 0x1BD11BDAu;
    x0 += k0; x1 += k1;
#define TFR(r) { x0 += x1; x1 = rotl32(x1, (r)); x1 ^= x0; }
    TFR(13) TFR(15) TFR(26) TFR(6)   x0 += k1;  x1 += ks2 + 1u;
    TFR(17) TFR(29) TFR(16) TFR(24)  x0 += ks2; x1 += k0 + 2u;
    TFR(13) TFR(15) TFR(26) TFR(6)   x0 += k0;  x1 += k1 + 3u;
    TFR(17) TFR(29) TFR(16) TFR(24)  x0 += k1;  x1 += ks2 + 4u;
    TFR(13) TFR(15) TFR(26) TFR(6)   x0 += ks2; x1 += k0 + 5u;
#undef TFR
    o0 = x0; o1 = x1;
}

// partitionable random_bits (bit_width=32) for flat index < 2^32:
// counts are uint64 iota -> (hi=0, lo=idx); result = bits1 ^ bits2
__device__ __forceinline__ uint32_t rb32(uint32_t k0, uint32_t k1, uint32_t idx) {
    uint32_t a, b; tf2x32(k0, k1, 0u, idx, a, b); return a ^ b;
}

// JAX uniform [0,1): bitcast(bits>>9 | 1.0f) - 1.0f
__device__ __forceinline__ float u01f(uint32_t bits) {
    return __uint_as_float((bits >> 9) | 0x3f800000u) - 1.0f;
}
__device__ __forceinline__ float unif(uint32_t bits, float lo, float hi) {
    return fmaxf(lo, u01f(bits) * (hi - lo) + lo);
}

struct SampleParams {
    float m00, m01, m10, m11, tx, ty;
    float br, ct, st;
    float top, bot, left, right;
    float gd, gl;
    float mean;
    uint32_t kv0, kv1;
    int flip, blur, eapply, gapply;
};

__global__ void __launch_bounds__(NTHREADS, 2)
aug_kernel(const float* __restrict__ gin, float* __restrict__ gout) {
    extern __shared__ float smem[];
    float* sA = smem;         // input sample, later reused as color-jittered z
    float* sB = smem + CHW;   // warped + flipped y
    __shared__ SampleParams P;
    __shared__ float red[NTHREADS];
    __shared__ uint32_t K1[12];   // level-1 keys: kg,kf,kc,kb,ke,km
    __shared__ uint32_t K2[30];   // level-2 keys
    __shared__ float U[17];

    const int b = blockIdx.x;
    const int tid = threadIdx.x;

    // ---------------- per-sample parameters (warp 0) ----------------
    if (tid < 32) {
        const int lane = tid;
        uint32_t o0, o1;
        // split(key(42)=(0,42), 6): key_j = tf(key, 0, j)
        if (lane < 6) {
            tf2x32(0u, 42u, 0u, (uint32_t)lane, o0, o1);
            K1[2 * lane] = o0; K1[2 * lane + 1] = o1;
        }
        __syncwarp();
        // level-2 splits: kg->4 @K2[0..7], kc->3 @K2[8..13], ke->6 @K2[14..25], km->2 @K2[26..29]
        if (lane < 4) {
            tf2x32(K1[0], K1[1], 0u, (uint32_t)lane, o0, o1);
            K2[2 * lane] = o0; K2[2 * lane + 1] = o1;
        } else if (lane < 7) {
            int i = lane - 4;
            tf2x32(K1[4], K1[5], 0u, (uint32_t)i, o0, o1);
            K2[8 + 2 * i] = o0; K2[9 + 2 * i] = o1;
        } else if (lane < 13) {
            int i = lane - 7;
            tf2x32(K1[8], K1[9], 0u, (uint32_t)i, o0, o1);
            K2[14 + 2 * i] = o0; K2[15 + 2 * i] = o1;
        } else if (lane < 15) {
            int i = lane - 13;
            tf2x32(K1[10], K1[11], 0u, (uint32_t)i, o0, o1);
            K2[26 + 2 * i] = o0; K2[27 + 2 * i] = o1;
        }
        __syncwarp();
        const uint32_t ub = (uint32_t)b;
        const float DEG = (float)(3.14159265358979323846 / 180.0);
        switch (lane) {
            case 0:  U[0]  = unif(rb32(K2[0],  K2[1],  ub), -25.f, 25.f) * DEG; break;  // ang
            case 1:  U[1]  = unif(rb32(K2[2],  K2[3],  ub), -15.f, 15.f) * DEG; break;  // shear
            case 2:  U[2]  = unif(rb32(K2[4],  K2[5],  ub), 0.85f, 1.15f); break;       // scale
            case 3:  U[3]  = unif(rb32(K2[6],  K2[7],  2u*ub),    -0.15f, 0.15f); break; // trn x
            case 4:  U[4]  = unif(rb32(K2[6],  K2[7],  2u*ub+1u), -0.15f, 0.15f); break; // trn y
            case 5:  U[5]  = u01f(rb32(K1[2],  K1[3],  ub)); break;                      // flip u
            case 6:  U[6]  = unif(rb32(K2[8],  K2[9],  ub), 0.7f, 1.3f); break;          // bright
            case 7:  U[7]  = unif(rb32(K2[10], K2[11], ub), 0.7f, 1.3f); break;          // contrast
            case 8:  U[8]  = unif(rb32(K2[12], K2[13], ub), 0.8f, 1.2f); break;          // sat
            case 9:  U[9]  = u01f(rb32(K1[6],  K1[7],  ub)); break;                      // blur u
            case 10: U[10] = unif(rb32(K2[14], K2[15], ub), 0.02f, 0.1f); break;         // area u
            case 11: U[11] = unif(rb32(K2[16], K2[17], ub), 0.3f, 3.0f); break;          // ratio
            case 12: U[12] = u01f(rb32(K2[18], K2[19], ub)); break;                      // top u
            case 13: U[13] = u01f(rb32(K2[20], K2[21], ub)); break;                      // left u
            case 14: U[14] = u01f(rb32(K2[24], K2[25], ub)); break;                      // erase apply u
            case 15: U[15] = floorf(unif(rb32(K2[26], K2[27], ub), 8.f, 32.f)); break;   // grid d
            case 16: U[16] = u01f(rb32(K2[28], K2[29], ub)); break;                      // grid apply u
            default: break;
        }
        __syncwarp();
        if (lane == 0) {
            float ang = U[0], shr = U[1], scl = U[2];
            float c = cosf(ang), s = sinf(ang), t = tanf(shr);
            P.m00 = (c - t * (-s)) / scl;
            P.m01 = (s - t * c) / scl;
            P.m10 = (-s) / scl;
            P.m11 = c / scl;
            P.tx = U[3] * 64.0f;
            P.ty = U[4] * 64.0f;
            P.flip = (U[5] < 0.6f);
            P.br = U[6]; P.ct = U[7]; P.st = U[8];
            P.blur = (U[9] < 0.3f);
            float area = (U[10] * 64.0f) * 64.0f;
            float ratio = U[11];
            float eh = fminf(fmaxf(sqrtf(area * ratio), 1.0f), 64.0f);
            float ew = fminf(fmaxf(sqrtf(area / ratio), 1.0f), 64.0f);
            P.top = U[12] * (64.0f - eh);   P.bot = P.top + eh;
            P.left = U[13] * (64.0f - ew);  P.right = P.left + ew;
            P.eapply = (U[14] < 0.3f);
            P.gd = U[15]; P.gl = floorf(U[15] * 0.6f);
            P.gapply = (U[16] < 0.3f);
            P.kv0 = K2[22]; P.kv1 = K2[23];
        }
    }

    // ---------------- load input sample into SMEM (coalesced) ----------------
    {
        const float4* gin4 = (const float4*)(gin + (size_t)b * CHW);
        float4* sA4 = (float4*)sA;
        for (int i = tid; i < CHW / 4; i += NTHREADS) sA4[i] = gin4[i];
    }
    __syncthreads();

    // ---------------- phase 1: affine warp + hflip -> sB; accumulate sum ----
    const float m00 = P.m00, m01 = P.m01, m10 = P.m10, m11 = P.m11;
    const float tx = P.tx, ty = P.ty;
    const bool flip = P.flip;
    float lsum = 0.f;
    for (int p = tid; p < HWpx; p += NTHREADS) {
        int h = p >> 6, w = p & 63;
        float gx = (float)w - 31.5f;
        float gy = (float)h - 31.5f;
        float sx = m00 * gx + m01 * gy - tx + 31.5f;
        float sy = m10 * gx + m11 * gy - ty + 31.5f;
        float x0f = floorf(sx), y0f = floorf(sy);
        float wx = sx - x0f, wy = sy - y0f;
        int x0 = (int)x0f, y0 = (int)y0f;
        int x1 = x0 + 1, y1 = y0 + 1;
        bool vx0 = (x0 >= 0) && (x0 < 64);
        bool vx1 = (x1 >= 0) && (x1 < 64);
        bool vy0 = (y0 >= 0) && (y0 < 64);
        bool vy1 = (y1 >= 0) && (y1 < 64);
        int cx0 = min(max(x0, 0), 63), cx1 = min(max(x1, 0), 63);
        int cy0 = min(max(y0, 0), 63), cy1 = min(max(y1, 0), 63);
        float w00 = (1.f - wx) * (1.f - wy), w01 = wx * (1.f - wy);
        float w10 = (1.f - wx) * wy,         w11 = wx * wy;
        int o00 = cy0 * 64 + cx0, o01 = cy0 * 64 + cx1;
        int o10 = cy1 * 64 + cx0, o11 = cy1 * 64 + cx1;
        bool v00 = vx0 && vy0, v01 = vx1 && vy0, v10 = vx0 && vy1, v11 = vx1 && vy1;
        int wd = flip ? (63 - w) : w;
        #pragma unroll
        for (int c = 0; c < 3; c++) {
            const float* img = sA + c * HWpx;
            float a0 = v00 ? img[o00] : 0.f;
            float a1 = v01 ? img[o01] : 0.f;
            float a2 = v10 ? img[o10] : 0.f;
            float a3 = v11 ? img[o11] : 0.f;
            float v = a0 * w00 + a1 * w01 + a2 * w10 + a3 * w11;
            sB[c * HWpx + h * 64 + wd] = v;
            lsum += v;
        }
    }
    red[tid] = lsum;
    __syncthreads();
    for (int s2 = NTHREADS / 2; s2 > 0; s2 >>= 1) {
        if (tid < s2) red[tid] += red[tid + s2];
        __syncthreads();
    }
    if (tid == 0) P.mean = (P.br * red[0]) / 12288.0f;
    __syncthreads();

    // ---------------- phase 2: color jitter (brightness/contrast/saturation) -> sA
    const float br = P.br, ct = P.ct, st = P.st, mean = P.mean;
    for (int p = tid; p < HWpx; p += NTHREADS) {
        float r  = sB[p], g = sB[HWpx + p], bl = sB[2 * HWpx + p];
        float xr = (r  * br - mean) * ct + mean;
        float xg = (g  * br - mean) * ct + mean;
        float xb = (bl * br - mean) * ct + mean;
        float gray = 0.299f * xr + 0.587f * xg + 0.114f * xb;
        sA[p]            = gray + (xr - gray) * st;
        sA[HWpx + p]     = gray + (xg - gray) * st;
        sA[2 * HWpx + p] = gray + (xb - gray) * st;
    }
    __syncthreads();

    // ---------------- phase 3: blur / erase / grid mask / clamp -> gout -----
    const bool doblur = P.blur;
    const bool eap = P.eapply, gap = P.gapply;
    const float top = P.top, bot = P.bot, left = P.left, right = P.right;
    const float gd = P.gd, gl = P.gl;
    const uint32_t kv0 = P.kv0, kv1 = P.kv1;
    float* o = gout + (size_t)b * CHW;
    for (int p = tid; p < HWpx; p += NTHREADS) {
        int h = p >> 6, w = p & 63;
        float v0, v1, v2;
        if (doblur) {
            const float kw[3] = {0.25f, 0.5f, 0.25f};
            float a0 = 0.f, a1 = 0.f, a2 = 0.f;
            #pragma unroll
            for (int dy = 0; dy < 3; dy++) {
                int hh = h + dy - 1;
                if (hh < 0 || hh > 63) continue;
                #pragma unroll
                for (int dx = 0; dx < 3; dx++) {
                    int ww = w + dx - 1;
                    if (ww < 0 || ww > 63) continue;
                    float wt = kw[dy] * kw[dx];
                    int off = hh * 64 + ww;
                    a0 += sA[off] * wt;
                    a1 += sA[HWpx + off] * wt;
                    a2 += sA[2 * HWpx + off] * wt;
                }
            }
            v0 = a0; v1 = a1; v2 = a2;
        } else {
            v0 = sA[p]; v1 = sA[HWpx + p]; v2 = sA[2 * HWpx + p];
        }
        float hf = (float)h, wf = (float)w;
        if (eap && hf >= top && hf < bot && wf >= left && wf < right) {
            uint32_t base = ((uint32_t)b * 3u) * 4096u + (uint32_t)p;
            v0 = u01f(rb32(kv0, kv1, base));
            v1 = u01f(rb32(kv0, kv1, base + 4096u));
            v2 = u01f(rb32(kv0, kv1, base + 8192u));
        }
        if (gap && fmodf(hf, gd) < gl && fmodf(wf, gd) < gl) {
            v0 = 0.f; v1 = 0.f; v2 = 0.f;
        }
        o[p]            = fminf(fmaxf(v0, 0.f), 1.f);
        o[HWpx + p]     = fminf(fmaxf(v1, 0.f), 1.f);
        o[2 * HWpx + p] = fminf(fmaxf(v2, 0.f), 1.f);
    }
}

extern "C" void kernel_launch(void* const* d_in, const int* in_sizes, int n_in,
                              void* d_out, int out_size) {
    (void)in_sizes; (void)n_in; (void)out_size;
    const float* x = (const float*)d_in[0];
    float* out = (float*)d_out;
    cudaFuncSetAttribute(aug_kernel, cudaFuncAttributeMaxDynamicSharedMemorySize,
                         2 * CHW * (int)sizeof(float));
    aug_kernel<<<BATCH, NTHREADS, 2 * CHW * sizeof(float)>>>(x, out);
}

// round 2
// speedup vs baseline: 1.1584x; 1.1584x over previous
#include <cuda_runtime.h>
#include <stdint.h>

// ============================================================================
// EnhancedAntiOverfittingAugmentation — fused single-kernel implementation.
// One CTA per sample (2048 CTAs). Phases:
//   1) affine warp + hflip (SMEM gather) -> sB, accumulate sum
//   2) fused color-jitter (affine: alpha*x + beta*gray + delta) + optional
//      3x3 blur (linear, commutes with jitter; SAME-pad handled via coverage
//      factor S) + random erasing + grid mask + clamp -> global out.
// Randomness replicates JAX Threefry-2x32, threefry_partitionable=True.
// 512 threads/CTA, 96KB dynamic SMEM, 2 CTAs/SM.
// ============================================================================

#define NTHREADS 512
#define BATCH 2048
#define HWpx 4096
#define CHW 12288

__device__ __forceinline__ uint32_t rotl32(uint32_t v, int d) {
    return (v << d) | (v >> (32 - d));
}

// Threefry-2x32, 20 rounds, exactly as in jax._src.prng
__device__ __forceinline__ void tf2x32(uint32_t k0, uint32_t k1,
                                       uint32_t x0, uint32_t x1,
                                       uint32_t &o0, uint32_t &o1) {
    const uint32_t ks2 = k0 ^ k1 ^ 0x1BD11BDAu;
    x0 += k0; x1 += k1;
#define TFR(r) { x0 += x1; x1 = rotl32(x1, (r)); x1 ^= x0; }
    TFR(13) TFR(15) TFR(26) TFR(6)   x0 += k1;  x1 += ks2 + 1u;
    TFR(17) TFR(29) TFR(16) TFR(24)  x0 += ks2; x1 += k0 + 2u;
    TFR(13) TFR(15) TFR(26) TFR(6)   x0 += k0;  x1 += k1 + 3u;
    TFR(17) TFR(29) TFR(16) TFR(24)  x0 += k1;  x1 += ks2 + 4u;
    TFR(13) TFR(15) TFR(26) TFR(6)   x0 += ks2; x1 += k0 + 5u;
#undef TFR
    o0 = x0; o1 = x1;
}

__device__ __forceinline__ uint32_t rb32(uint32_t k0, uint32_t k1, uint32_t idx) {
    uint32_t a, b; tf2x32(k0, k1, 0u, idx, a, b); return a ^ b;
}

__device__ __forceinline__ float u01f(uint32_t bits) {
    return __uint_as_float((bits >> 9) | 0x3f800000u) - 1.0f;
}
__device__ __forceinline__ float unif(uint32_t bits, float lo, float hi) {
    return fmaxf(lo, u01f(bits) * (hi - lo) + lo);
}

struct SampleParams {
    float m00, m01, m10, m11, tx, ty;
    float br, ct, st;
    float top, bot, left, right;
    float gd, gl;
    float alpha, beta, delta;
    uint32_t kv0, kv1;
    int flip, blur, eapply, gapply;
};

__global__ void __launch_bounds__(NTHREADS, 2)
aug_kernel(const float* __restrict__ gin, float* __restrict__ gout) {
    extern __shared__ float smem[];
    float* sA = smem;         // input sample
    float* sB = smem + CHW;   // warped + flipped
    __shared__ SampleParams P;
    __shared__ float red[NTHREADS / 32];
    __shared__ uint32_t K1[12];
    __shared__ uint32_t K2[30];
    __shared__ float U[17];

    const int b = blockIdx.x;
    const int tid = threadIdx.x;

    // ---------------- per-sample parameters (warp 0) ----------------
    if (tid < 32) {
        const int lane = tid;
        uint32_t o0, o1;
        if (lane < 6) {
            tf2x32(0u, 42u, 0u, (uint32_t)lane, o0, o1);
            K1[2 * lane] = o0; K1[2 * lane + 1] = o1;
        }
        __syncwarp();
        if (lane < 4) {
            tf2x32(K1[0], K1[1], 0u, (uint32_t)lane, o0, o1);
            K2[2 * lane] = o0; K2[2 * lane + 1] = o1;
        } else if (lane < 7) {
            int i = lane - 4;
            tf2x32(K1[4], K1[5], 0u, (uint32_t)i, o0, o1);
            K2[8 + 2 * i] = o0; K2[9 + 2 * i] = o1;
        } else if (lane < 13) {
            int i = lane - 7;
            tf2x32(K1[8], K1[9], 0u, (uint32_t)i, o0, o1);
            K2[14 + 2 * i] = o0; K2[15 + 2 * i] = o1;
        } else if (lane < 15) {
            int i = lane - 13;
            tf2x32(K1[10], K1[11], 0u, (uint32_t)i, o0, o1);
            K2[26 + 2 * i] = o0; K2[27 + 2 * i] = o1;
        }
        __syncwarp();
        const uint32_t ub = (uint32_t)b;
        const float DEG = (float)(3.14159265358979323846 / 180.0);
        switch (lane) {
            case 0:  U[0]  = unif(rb32(K2[0],  K2[1],  ub), -25.f, 25.f) * DEG; break;
            case 1:  U[1]  = unif(rb32(K2[2],  K2[3],  ub), -15.f, 15.f) * DEG; break;
            case 2:  U[2]  = unif(rb32(K2[4],  K2[5],  ub), 0.85f, 1.15f); break;
            case 3:  U[3]  = unif(rb32(K2[6],  K2[7],  2u*ub),    -0.15f, 0.15f); break;
            case 4:  U[4]  = unif(rb32(K2[6],  K2[7],  2u*ub+1u), -0.15f, 0.15f); break;
            case 5:  U[5]  = u01f(rb32(K1[2],  K1[3],  ub)); break;
            case 6:  U[6]  = unif(rb32(K2[8],  K2[9],  ub), 0.7f, 1.3f); break;
            case 7:  U[7]  = unif(rb32(K2[10], K2[11], ub), 0.7f, 1.3f); break;
            case 8:  U[8]  = unif(rb32(K2[12], K2[13], ub), 0.8f, 1.2f); break;
            case 9:  U[9]  = u01f(rb32(K1[6],  K1[7],  ub)); break;
            case 10: U[10] = unif(rb32(K2[14], K2[15], ub), 0.02f, 0.1f); break;
            case 11: U[11] = unif(rb32(K2[16], K2[17], ub), 0.3f, 3.0f); break;
            case 12: U[12] = u01f(rb32(K2[18], K2[19], ub)); break;
            case 13: U[13] = u01f(rb32(K2[20], K2[21], ub)); break;
            case 14: U[14] = u01f(rb32(K2[24], K2[25], ub)); break;
            case 15: U[15] = floorf(unif(rb32(K2[26], K2[27], ub), 8.f, 32.f)); break;
            case 16: U[16] = u01f(rb32(K2[28], K2[29], ub)); break;
            default: break;
        }
        __syncwarp();
        if (lane == 0) {
            float ang = U[0], shr = U[1], scl = U[2];
            float c = cosf(ang), s = sinf(ang), t = tanf(shr);
            P.m00 = (c - t * (-s)) / scl;
            P.m01 = (s - t * c) / scl;
            P.m10 = (-s) / scl;
            P.m11 = c / scl;
            P.tx = U[3] * 64.0f;
            P.ty = U[4] * 64.0f;
            P.flip = (U[5] < 0.6f);
            P.br = U[6]; P.ct = U[7]; P.st = U[8];
            P.blur = (U[9] < 0.3f);
            float area = (U[10] * 64.0f) * 64.0f;
            float ratio = U[11];
            float eh = fminf(fmaxf(sqrtf(area * ratio), 1.0f), 64.0f);
            float ew = fminf(fmaxf(sqrtf(area / ratio), 1.0f), 64.0f);
            P.top = U[12] * (64.0f - eh);   P.bot = P.top + eh;
            P.left = U[13] * (64.0f - ew);  P.right = P.left + ew;
            P.eapply = (U[14] < 0.3f);
            P.gd = U[15]; P.gl = floorf(U[15] * 0.6f);
            P.gapply = (U[16] < 0.3f);
            P.kv0 = K2[22]; P.kv1 = K2[23];
        }
    }

    // ---------------- load input sample into SMEM (coalesced float4) --------
    {
        const float4* gin4 = (const float4*)(gin + (size_t)b * CHW);
        float4* sA4 = (float4*)sA;
        #pragma unroll
        for (int i = tid; i < CHW / 4; i += NTHREADS) sA4[i] = gin4[i];
    }
    __syncthreads();

    // ---------------- phase 1: affine warp + hflip -> sB; accumulate sum ----
    const float m00 = P.m00, m01 = P.m01, m10 = P.m10, m11 = P.m11;
    const float tx = P.tx, ty = P.ty;
    const bool flip = P.flip;
    float lsum = 0.f;
    #pragma unroll
    for (int p = tid; p < HWpx; p += NTHREADS) {
        int h = p >> 6, w = p & 63;
        float gx = (float)w - 31.5f;
        float gy = (float)h - 31.5f;
        float sx = m00 * gx + m01 * gy - tx + 31.5f;
        float sy = m10 * gx + m11 * gy - ty + 31.5f;
        float x0f = floorf(sx), y0f = floorf(sy);
        float wx = sx - x0f, wy = sy - y0f;
        int x0 = (int)x0f, y0 = (int)y0f;
        int x1 = x0 + 1, y1 = y0 + 1;
        bool vx0 = (x0 >= 0) && (x0 < 64);
        bool vx1 = (x1 >= 0) && (x1 < 64);
        bool vy0 = (y0 >= 0) && (y0 < 64);
        bool vy1 = (y1 >= 0) && (y1 < 64);
        int cx0 = min(max(x0, 0), 63), cx1 = min(max(x1, 0), 63);
        int cy0 = min(max(y0, 0), 63), cy1 = min(max(y1, 0), 63);
        float w00 = (1.f - wx) * (1.f - wy), w01 = wx * (1.f - wy);
        float w10 = (1.f - wx) * wy,         w11 = wx * wy;
        int o00 = cy0 * 64 + cx0, o01 = cy0 * 64 + cx1;
        int o10 = cy1 * 64 + cx0, o11 = cy1 * 64 + cx1;
        bool v00 = vx0 && vy0, v01 = vx1 && vy0, v10 = vx0 && vy1, v11 = vx1 && vy1;
        int wd = flip ? (63 - w) : w;
        #pragma unroll
        for (int c = 0; c < 3; c++) {
            const float* img = sA + c * HWpx;
            float a0 = v00 ? img[o00] : 0.f;
            float a1 = v01 ? img[o01] : 0.f;
            float a2 = v10 ? img[o10] : 0.f;
            float a3 = v11 ? img[o11] : 0.f;
            float v = a0 * w00 + a1 * w01 + a2 * w10 + a3 * w11;
            sB[c * HWpx + h * 64 + wd] = v;
            lsum += v;
        }
    }
    // warp-shuffle reduction, then cross-warp via small smem
    #pragma unroll
    for (int off = 16; off > 0; off >>= 1)
        lsum += __shfl_xor_sync(0xffffffffu, lsum, off);
    if ((tid & 31) == 0) red[tid >> 5] = lsum;
    __syncthreads();
    if (tid == 0) {
        float s = 0.f;
        #pragma unroll
        for (int i = 0; i < NTHREADS / 32; i++) s += red[i];
        float mean = (P.br * s) / 12288.0f;
        float bc = P.br * P.ct;
        P.alpha = P.st * bc;
        P.beta  = (1.0f - P.st) * bc;
        P.delta = mean * (1.0f - P.ct);
    }
    __syncthreads();

    // ---- phase 2 (fused): jitter-affine + blur + erase + gridmask + clamp --
    const bool doblur = P.blur;
    const bool eap = P.eapply, gap = P.gapply;
    const float top = P.top, bot = P.bot, left = P.left, right = P.right;
    const float gd = P.gd, gl = P.gl;
    const float alpha = P.alpha, beta = P.beta, delta = P.delta;
    const uint32_t kv0 = P.kv0, kv1 = P.kv1;
    float* o = gout + (size_t)b * CHW;

    #pragma unroll
    for (int j = 0; j < HWpx / (4 * NTHREADS); j++) {
        const int base = (tid + j * NTHREADS) * 4;  // 16B aligned, 4 consecutive px
        float4 R, G, Bc;
        float S4[4];  // blur coverage factor per pixel (1.0 if no blur)
        if (!doblur) {
            R  = *(const float4*)(sB + base);
            G  = *(const float4*)(sB + HWpx + base);
            Bc = *(const float4*)(sB + 2 * HWpx + base);
            S4[0] = S4[1] = S4[2] = S4[3] = 1.0f;
        } else {
            float rr[4], gg[4], bb[4];
            #pragma unroll
            for (int k = 0; k < 4; k++) {
                int p = base + k;
                int h = p >> 6, w = p & 63;
                const float kw[3] = {0.25f, 0.5f, 0.25f};
                float a0 = 0.f, a1 = 0.f, a2 = 0.f;
                #pragma unroll
                for (int dy = 0; dy < 3; dy++) {
                    int hh = h + dy - 1;
                    if (hh < 0 || hh > 63) continue;
                    #pragma unroll
                    for (int dx = 0; dx < 3; dx++) {
                        int ww = w + dx - 1;
                        if (ww < 0 || ww > 63) continue;
                        float wt = kw[dy] * kw[dx];
                        int off = hh * 64 + ww;
                        a0 += sB[off] * wt;
                        a1 += sB[HWpx + off] * wt;
                        a2 += sB[2 * HWpx + off] * wt;
                    }
                }
                rr[k] = a0; gg[k] = a1; bb[k] = a2;
                float ry = 1.0f - 0.25f * ((h == 0) + (h == 63));
                float rx = 1.0f - 0.25f * ((w == 0) + (w == 63));
                S4[k] = ry * rx;
            }
            R  = make_float4(rr[0], rr[1], rr[2], rr[3]);
            G  = make_float4(gg[0], gg[1], gg[2], gg[3]);
            Bc = make_float4(bb[0], bb[1], bb[2], bb[3]);
        }
        float4 O0, O1, O2;
        float* Rp = &R.x; float* Gp = &G.x; float* Bp = &Bc.x;
        float* O0p = &O0.x; float* O1p = &O1.x; float* O2p = &O2.x;
        #pragma unroll
        for (int k = 0; k < 4; k++) {
            int p = base + k;
            int h = p >> 6, w = p & 63;
            float r = Rp[k], g = Gp[k], bl = Bp[k];
            float gray = 0.299f * r + 0.587f * g + 0.114f * bl;
            float dd = delta * S4[k];
            float v0 = alpha * r  + beta * gray + dd;
            float v1 = alpha * g  + beta * gray + dd;
            float v2 = alpha * bl + beta * gray + dd;
            float hf = (float)h, wf = (float)w;
            if (eap && hf >= top && hf < bot && wf >= left && wf < right) {
                uint32_t rbase = ((uint32_t)b * 3u) * 4096u + (uint32_t)p;
                v0 = u01f(rb32(kv0, kv1, rbase));
                v1 = u01f(rb32(kv0, kv1, rbase + 4096u));
                v2 = u01f(rb32(kv0, kv1, rbase + 8192u));
            }
            if (gap && fmodf(hf, gd) < gl && fmodf(wf, gd) < gl) {
                v0 = 0.f; v1 = 0.f; v2 = 0.f;
            }
            O0p[k] = fminf(fmaxf(v0, 0.f), 1.f);
            O1p[k] = fminf(fmaxf(v1, 0.f), 1.f);
            O2p[k] = fminf(fmaxf(v2, 0.f), 1.f);
        }
        *(float4*)(o + base)            = O0;
        *(float4*)(o + HWpx + base)     = O1;
        *(float4*)(o + 2 * HWpx + base) = O2;
    }
}

extern "C" void kernel_launch(void* const* d_in, const int* in_sizes, int n_in,
                              void* d_out, int out_size) {
    (void)in_sizes; (void)n_in; (void)out_size;
    const float* x = (const float*)d_in[0];
    float* out = (float*)d_out;
    cudaFuncSetAttribute(aug_kernel, cudaFuncAttributeMaxDynamicSharedMemorySize,
                         2 * CHW * (int)sizeof(float));
    aug_kernel<<<BATCH, NTHREADS, 2 * CHW * sizeof(float)>>>(x, out);
}

// round 3
// speedup vs baseline: 1.2545x; 1.0830x over previous
#include <cuda_runtime.h>
#include <stdint.h>

// ============================================================================
// EnhancedAntiOverfittingAugmentation — fused single-kernel, round 3.
//  - zero-padded SMEM input plane (pad 2, row stride 72) -> unconditional
//    bilinear gathers (no validity predicates)
//  - bitmask grid/erase tests (no fmodf per pixel)
//  - separable 3x3 blur (h-pass reuses input plane as scratch)
//  - fused affine color jitter: out = alpha*x + beta*gray(x) + delta*S
// Randomness replicates JAX Threefry-2x32, threefry_partitionable=True.
// 512 threads/CTA, ~105KB dynamic SMEM, 2 CTAs/SM.
// ============================================================================

#define NTHREADS 512
#define BATCH 2048
#define HWpx 4096
#define CHW 12288
#define PSTRIDE 72            // padded row stride (floats)
#define PPLANE (68 * 72)      // padded plane floats (68 rows)
#define SA_FLOATS (3 * PPLANE)

__device__ __forceinline__ uint32_t rotl32(uint32_t v, int d) {
    return (v << d) | (v >> (32 - d));
}

// Threefry-2x32, 20 rounds, exactly as in jax._src.prng
__device__ __forceinline__ void tf2x32(uint32_t k0, uint32_t k1,
                                       uint32_t x0, uint32_t x1,
                                       uint32_t &o0, uint32_t &o1) {
    const uint32_t ks2 = k0 ^ k1 ^ 0x1BD11BDAu;
    x0 += k0; x1 += k1;
#define TFR(r) { x0 += x1; x1 = rotl32(x1, (r)); x1 ^= x0; }
    TFR(13) TFR(15) TFR(26) TFR(6)   x0 += k1;  x1 += ks2 + 1u;
    TFR(17) TFR(29) TFR(16) TFR(24)  x0 += ks2; x1 += k0 + 2u;
    TFR(13) TFR(15) TFR(26) TFR(6)   x0 += k0;  x1 += k1 + 3u;
    TFR(17) TFR(29) TFR(16) TFR(24)  x0 += k1;  x1 += ks2 + 4u;
    TFR(13) TFR(15) TFR(26) TFR(6)   x0 += ks2; x1 += k0 + 5u;
#undef TFR
    o0 = x0; o1 = x1;
}

__device__ __forceinline__ uint32_t rb32(uint32_t k0, uint32_t k1, uint32_t idx) {
    uint32_t a, b; tf2x32(k0, k1, 0u, idx, a, b); return a ^ b;
}

__device__ __forceinline__ float u01f(uint32_t bits) {
    return __uint_as_float((bits >> 9) | 0x3f800000u) - 1.0f;
}
__device__ __forceinline__ float unif(uint32_t bits, float lo, float hi) {
    return fmaxf(lo, u01f(bits) * (hi - lo) + lo);
}

struct SampleParams {
    float m00, m01, m10, m11, tx, ty;
    float br, ct, st;
    float top, bot, left, right;
    float gd, gl;
    float alpha, beta, delta;
    uint32_t kv0, kv1;
    int flip, blur, eapply, gapply;
};

__global__ void __launch_bounds__(NTHREADS, 2)
aug_kernel(const float* __restrict__ gin, float* __restrict__ gout) {
    extern __shared__ float smem[];
    float* sA = smem;              // padded input (later reused as h-blur scratch)
    float* sB = smem + SA_FLOATS;  // warped + flipped, 3x4096 compact
    __shared__ SampleParams P;
    __shared__ float red[NTHREADS / 32];
    __shared__ uint32_t K1[12];
    __shared__ uint32_t K2[30];
    __shared__ float U[17];
    __shared__ uint32_t gm_row[2], gm_col[2], er_row[2], er_col[2];

    const int b = blockIdx.x;
    const int tid = threadIdx.x;

    // ---------------- per-sample parameters (warp 0) ----------------
    if (tid < 32) {
        const int lane = tid;
        uint32_t o0, o1;
        if (lane < 6) {
            tf2x32(0u, 42u, 0u, (uint32_t)lane, o0, o1);
            K1[2 * lane] = o0; K1[2 * lane + 1] = o1;
        }
        __syncwarp();
        if (lane < 4) {
            tf2x32(K1[0], K1[1], 0u, (uint32_t)lane, o0, o1);
            K2[2 * lane] = o0; K2[2 * lane + 1] = o1;
        } else if (lane < 7) {
            int i = lane - 4;
            tf2x32(K1[4], K1[5], 0u, (uint32_t)i, o0, o1);
            K2[8 + 2 * i] = o0; K2[9 + 2 * i] = o1;
        } else if (lane < 13) {
            int i = lane - 7;
            tf2x32(K1[8], K1[9], 0u, (uint32_t)i, o0, o1);
            K2[14 + 2 * i] = o0; K2[15 + 2 * i] = o1;
        } else if (lane < 15) {
            int i = lane - 13;
            tf2x32(K1[10], K1[11], 0u, (uint32_t)i, o0, o1);
            K2[26 + 2 * i] = o0; K2[27 + 2 * i] = o1;
        }
        __syncwarp();
        const uint32_t ub = (uint32_t)b;
        const float DEG = (float)(3.14159265358979323846 / 180.0);
        switch (lane) {
            case 0:  U[0]  = unif(rb32(K2[0],  K2[1],  ub), -25.f, 25.f) * DEG; break;
            case 1:  U[1]  = unif(rb32(K2[2],  K2[3],  ub), -15.f, 15.f) * DEG; break;
            case 2:  U[2]  = unif(rb32(K2[4],  K2[5],  ub), 0.85f, 1.15f); break;
            case 3:  U[3]  = unif(rb32(K2[6],  K2[7],  2u*ub),    -0.15f, 0.15f); break;
            case 4:  U[4]  = unif(rb32(K2[6],  K2[7],  2u*ub+1u), -0.15f, 0.15f); break;
            case 5:  U[5]  = u01f(rb32(K1[2],  K1[3],  ub)); break;
            case 6:  U[6]  = unif(rb32(K2[8],  K2[9],  ub), 0.7f, 1.3f); break;
            case 7:  U[7]  = unif(rb32(K2[10], K2[11], ub), 0.7f, 1.3f); break;
            case 8:  U[8]  = unif(rb32(K2[12], K2[13], ub), 0.8f, 1.2f); break;
            case 9:  U[9]  = u01f(rb32(K1[6],  K1[7],  ub)); break;
            case 10: U[10] = unif(rb32(K2[14], K2[15], ub), 0.02f, 0.1f); break;
            case 11: U[11] = unif(rb32(K2[16], K2[17], ub), 0.3f, 3.0f); break;
            case 12: U[12] = u01f(rb32(K2[18], K2[19], ub)); break;
            case 13: U[13] = u01f(rb32(K2[20], K2[21], ub)); break;
            case 14: U[14] = u01f(rb32(K2[24], K2[25], ub)); break;
            case 15: U[15] = floorf(unif(rb32(K2[26], K2[27], ub), 8.f, 32.f)); break;
            case 16: U[16] = u01f(rb32(K2[28], K2[29], ub)); break;
            default: break;
        }
        __syncwarp();
        if (lane == 0) {
            float ang = U[0], shr = U[1], scl = U[2];
            float c = cosf(ang), s = sinf(ang), t = tanf(shr);
            P.m00 = (c - t * (-s)) / scl;
            P.m01 = (s - t * c) / scl;
            P.m10 = (-s) / scl;
            P.m11 = c / scl;
            P.tx = U[3] * 64.0f;
            P.ty = U[4] * 64.0f;
            P.flip = (U[5] < 0.6f);
            P.br = U[6]; P.ct = U[7]; P.st = U[8];
            P.blur = (U[9] < 0.3f);
            float area = (U[10] * 64.0f) * 64.0f;
            float ratio = U[11];
            float eh = fminf(fmaxf(sqrtf(area * ratio), 1.0f), 64.0f);
            float ew = fminf(fmaxf(sqrtf(area / ratio), 1.0f), 64.0f);
            P.top = U[12] * (64.0f - eh);   P.bot = P.top + eh;
            P.left = U[13] * (64.0f - ew);  P.right = P.left + ew;
            P.eapply = (U[14] < 0.3f);
            P.gd = U[15]; P.gl = floorf(U[15] * 0.6f);
            P.gapply = (U[16] < 0.3f);
            P.kv0 = K2[22]; P.kv1 = K2[23];
        }
    }

    // ---------------- zero the padded planes (all cells) ---------------------
    {
        float4* sA4 = (float4*)sA;
        const float4 z = make_float4(0.f, 0.f, 0.f, 0.f);
        #pragma unroll
        for (int i = tid; i < SA_FLOATS / 4; i += NTHREADS) sA4[i] = z;
    }
    __syncthreads();   // P visible; zeros complete

    // ---------------- bitmask precompute (warps 0-3) + interior load --------
    if (tid < 128) {
        int warp = tid >> 5, lane = tid & 31;
        float coord = (float)((warp & 1) * 32 + lane);
        bool gbit = fmodf(coord, P.gd) < P.gl;
        bool ebit = (warp < 2) ? (coord >= P.top && coord < P.bot)
                               : (coord >= P.left && coord < P.right);
        uint32_t gb = __ballot_sync(0xffffffffu, gbit);
        uint32_t eb = __ballot_sync(0xffffffffu, ebit);
        if (lane == 0) {
            if (warp == 0)      { gm_row[0] = gb; er_row[0] = eb; }
            else if (warp == 1) { gm_row[1] = gb; er_row[1] = eb; }
            else if (warp == 2) { gm_col[0] = gb; er_col[0] = eb; }
            else                { gm_col[1] = gb; er_col[1] = eb; }
        }
    }
    {
        const float4* gin4 = (const float4*)(gin + (size_t)b * CHW);
        #pragma unroll
        for (int i4 = tid; i4 < CHW / 4; i4 += NTHREADS) {
            int p = i4 << 2;
            int c = p >> 12;
            int q = p & 4095;
            int h = q >> 6, w = q & 63;
            *(float4*)(sA + c * PPLANE + (h + 2) * PSTRIDE + (w + 4)) = gin4[i4];
        }
    }
    __syncthreads();

    // ---------------- phase 1: affine warp + hflip -> sB; accumulate sum ----
    const float m00 = P.m00, m01 = P.m01, m10 = P.m10, m11 = P.m11;
    {
        const int w = tid & 63;
        const int h0 = tid >> 6;     // 0..7
        const int wd = P.flip ? (63 - w) : w;
        const float gx = (float)w - 31.5f;
        float sx = m00 * gx + m01 * ((float)h0 - 31.5f) - P.tx + 31.5f;
        float sy = m10 * gx + m11 * ((float)h0 - 31.5f) - P.ty + 31.5f;
        const float dx8 = 8.0f * m01, dy8 = 8.0f * m11;
        float lsum = 0.f;
        #pragma unroll
        for (int k = 0; k < 8; k++) {
            const int h = h0 + k * 8;
            float x0f = floorf(sx), y0f = floorf(sy);
            float wx = sx - x0f, wy = sy - y0f;
            int x0 = (int)x0f, y0 = (int)y0f;
            int xi = min(max(x0, -2), 64);
            int yi = min(max(y0, -2), 64);
            const float* im = sA + (yi + 2) * PSTRIDE + (xi + 4);
            float w11 = wx * wy;
            float w01 = wx - w11;
            float w10 = wy - w11;
            float w00 = 1.0f - wx - wy + w11;
            const int sbo = h * 64 + wd;
            #pragma unroll
            for (int c = 0; c < 3; c++) {
                const float* p0 = im + c * PPLANE;
                float v = p0[0] * w00 + p0[1] * w01 + p0[PSTRIDE] * w10 + p0[PSTRIDE + 1] * w11;
                sB[c * HWpx + sbo] = v;
                lsum += v;
            }
            sx += dx8; sy += dy8;
        }
        #pragma unroll
        for (int off = 16; off > 0; off >>= 1)
            lsum += __shfl_xor_sync(0xffffffffu, lsum, off);
        if ((tid & 31) == 0) red[tid >> 5] = lsum;
    }
    __syncthreads();
    if (tid == 0) {
        float s = 0.f;
        #pragma unroll
        for (int i = 0; i < NTHREADS / 32; i++) s += red[i];
        float mean = (P.br * s) / 12288.0f;
        float bc = P.br * P.ct;
        P.alpha = P.st * bc;
        P.beta  = (1.0f - P.st) * bc;
        P.delta = mean * (1.0f - P.ct);
    }
    __syncthreads();

    const bool doblur = P.blur;
    float* hA = sA;   // reuse padded plane space as compact 3x4096 h-blur scratch

    // ---------------- optional horizontal blur pass (sB -> hA) --------------
    if (doblur) {
        #pragma unroll
        for (int p = tid; p < HWpx; p += NTHREADS) {
            int w = p & 63;
            #pragma unroll
            for (int c = 0; c < 3; c++) {
                int i = c * HWpx + p;
                float l = (w > 0)  ? sB[i - 1] : 0.f;
                float r = (w < 63) ? sB[i + 1] : 0.f;
                hA[i] = 0.5f * sB[i] + 0.25f * (l + r);
            }
        }
        __syncthreads();
    }

    // ---- final: vertical blur (opt) + jitter-affine + erase + grid + clamp -
    const bool eap = P.eapply, gap = P.gapply;
    const float alpha = P.alpha, beta = P.beta, delta = P.delta;
    const uint32_t kv0 = P.kv0, kv1 = P.kv1;
    float* o = gout + (size_t)b * CHW;

    #pragma unroll
    for (int j = 0; j < 2; j++) {
        const int p4 = tid + j * NTHREADS;
        const int base = p4 << 2;           // 4 consecutive px, same row
        const int h = base >> 6;
        const int wb = base & 63;
        const bool ghit_h = gap && ((gm_row[h >> 5] >> (h & 31)) & 1u);
        const bool ehit_h = eap && ((er_row[h >> 5] >> (h & 31)) & 1u);
        float vr[4], vg[4], vb[4], Sv[4];
        if (!doblur) {
            float4 R  = *(const float4*)(sB + base);
            float4 G  = *(const float4*)(sB + HWpx + base);
            float4 Bv = *(const float4*)(sB + 2 * HWpx + base);
            vr[0]=R.x; vr[1]=R.y; vr[2]=R.z; vr[3]=R.w;
            vg[0]=G.x; vg[1]=G.y; vg[2]=G.z; vg[3]=G.w;
            vb[0]=Bv.x;vb[1]=Bv.y;vb[2]=Bv.z;vb[3]=Bv.w;
            Sv[0]=Sv[1]=Sv[2]=Sv[3]=1.0f;
        } else {
            const float ry = 1.0f - 0.25f * ((h == 0) + (h == 63));
            const bool hasU = (h > 0), hasD = (h < 63);
            #pragma unroll
            for (int k = 0; k < 4; k++) {
                int p = base + k;
                int w = wb + k;
                #pragma unroll
                for (int c = 0; c < 3; c++) {
                    int i = c * HWpx + p;
                    float u = hasU ? hA[i - 64] : 0.f;
                    float d = hasD ? hA[i + 64] : 0.f;
                    float v = 0.5f * hA[i] + 0.25f * (u + d);
                    if (c == 0) vr[k] = v; else if (c == 1) vg[k] = v; else vb[k] = v;
                }
                Sv[k] = ry * (1.0f - 0.25f * ((w == 0) + (w == 63)));
            }
        }
        float4 O0, O1, O2;
        float* O0p = &O0.x; float* O1p = &O1.x; float* O2p = &O2.x;
        #pragma unroll
        for (int k = 0; k < 4; k++) {
            int w = wb + k;
            float r = vr[k], g = vg[k], bl = vb[k];
            float gray = 0.299f * r + 0.587f * g + 0.114f * bl;
            float dd = delta * Sv[k];
            float v0 = alpha * r  + beta * gray + dd;
            float v1 = alpha * g  + beta * gray + dd;
            float v2 = alpha * bl + beta * gray + dd;
            if (ehit_h && ((er_col[w >> 5] >> (w & 31)) & 1u)) {
                uint32_t rbase = ((uint32_t)b * 3u) * 4096u + (uint32_t)(base + k);
                v0 = u01f(rb32(kv0, kv1, rbase));
                v1 = u01f(rb32(kv0, kv1, rbase + 4096u));
                v2 = u01f(rb32(kv0, kv1, rbase + 8192u));
            }
            if (ghit_h && ((gm_col[w >> 5] >> (w & 31)) & 1u)) {
                v0 = 0.f; v1 = 0.f; v2 = 0.f;
            }
            O0p[k] = fminf(fmaxf(v0, 0.f), 1.f);
            O1p[k] = fminf(fmaxf(v1, 0.f), 1.f);
            O2p[k] = fminf(fmaxf(v2, 0.f), 1.f);
        }
        *(float4*)(o + base)            = O0;
        *(float4*)(o + HWpx + base)     = O1;
        *(float4*)(o + 2 * HWpx + base) = O2;
    }
}

extern "C" void kernel_launch(void* const* d_in, const int* in_sizes, int n_in,
                              void* d_out, int out_size) {
    (void)in_sizes; (void)n_in; (void)out_size;
    const float* x = (const float*)d_in[0];
    float* out = (float*)d_out;
    const int smem_bytes = (SA_FLOATS + CHW) * (int)sizeof(float);
    cudaFuncSetAttribute(aug_kernel, cudaFuncAttributeMaxDynamicSharedMemorySize,
                         smem_bytes);
    aug_kernel<<<BATCH, NTHREADS, smem_bytes>>>(x, out);
}

// round 4
// speedup vs baseline: 1.2562x; 1.0013x over previous
#include <cuda_runtime.h>
#include <stdint.h>

// ============================================================================
// EnhancedAntiOverfittingAugmentation — fused single-kernel, round 4.
//  - input staged as RG-interleaved plane (LDS.64 taps) + B plane (LDS.32)
//    with 2px zero borders -> unconditional bilinear gathers, 8 LDS/px
//  - border-only zeroing (one float4 store per thread, no full-plane pass)
//  - 3 barriers total: [params+ballots+zero+load] | phase1 | phase2
//    (mean finished per-warp via shuffles, no extra barrier)
//  - bitmask grid/erase tests; separable blur; fused affine color jitter
// Randomness replicates JAX Threefry-2x32, threefry_partitionable=True.
// 512 threads/CTA, 103.25KB dynamic SMEM, 2 CTAs/SM.
// ============================================================================

#define NTHREADS 512
#define BATCH 2048
#define HWpx 4096
#define CHW 12288
#define RGSTRIDE 136              // floats per row of RG plane (68 px * 2)
#define OFF_B (68 * 136)          // 9248 floats
#define BSTRIDE 72                // floats per row of B plane
#define OFF_W (OFF_B + 68 * 72)   // 9248 + 4896 = 14144 floats
#define SMEM_FLOATS (OFF_W + CHW) // 26432 floats = 105728 B

__device__ __forceinline__ uint32_t rotl32(uint32_t v, int d) {
    return (v << d) | (v >> (32 - d));
}

// Threefry-2x32, 20 rounds, exactly as in jax._src.prng
__device__ __forceinline__ void tf2x32(uint32_t k0, uint32_t k1,
                                       uint32_t x0, uint32_t x1,
                                       uint32_t &o0, uint32_t &o1) {
    const uint32_t ks2 = k0 ^ k1 ^ 0x1BD11BDAu;
    x0 += k0; x1 += k1;
#define TFR(r) { x0 += x1; x1 = rotl32(x1, (r)); x1 ^= x0; }
    TFR(13) TFR(15) TFR(26) TFR(6)   x0 += k1;  x1 += ks2 + 1u;
    TFR(17) TFR(29) TFR(16) TFR(24)  x0 += ks2; x1 += k0 + 2u;
    TFR(13) TFR(15) TFR(26) TFR(6)   x0 += k0;  x1 += k1 + 3u;
    TFR(17) TFR(29) TFR(16) TFR(24)  x0 += k1;  x1 += ks2 + 4u;
    TFR(13) TFR(15) TFR(26) TFR(6)   x0 += ks2; x1 += k0 + 5u;
#undef TFR
    o0 = x0; o1 = x1;
}

__device__ __forceinline__ uint32_t rb32(uint32_t k0, uint32_t k1, uint32_t idx) {
    uint32_t a, b; tf2x32(k0, k1, 0u, idx, a, b); return a ^ b;
}

__device__ __forceinline__ float u01f(uint32_t bits) {
    return __uint_as_float((bits >> 9) | 0x3f800000u) - 1.0f;
}
__device__ __forceinline__ float unif(uint32_t bits, float lo, float hi) {
    return fmaxf(lo, u01f(bits) * (hi - lo) + lo);
}

struct SampleParams {
    float m00, m01, m10, m11, tx, ty;
    float br, ct, st;
    float top, bot, left, right;
    float gd, gl;
    uint32_t kv0, kv1;
    int flip, blur, eapply, gapply;
};

__global__ void __launch_bounds__(NTHREADS, 2)
aug_kernel(const float* __restrict__ gin, float* __restrict__ gout) {
    extern __shared__ float smem[];
    float* sRG = smem;             // RG interleaved, 68 rows x 68 px x 2
    float* sBp = smem + OFF_B;     // B plane, 68 rows x stride 72
    float* sW  = smem + OFF_W;     // warped+flipped, 3 x 4096 planar
    __shared__ SampleParams P;
    __shared__ float red[NTHREADS / 32];
    __shared__ uint32_t K1[12];
    __shared__ uint32_t K2[30];
    __shared__ float U[17];
    __shared__ uint32_t gm[2], er_row[2], er_col[2];

    const int b = blockIdx.x;
    const int tid = threadIdx.x;

    // ---------------- per-sample parameters + bitmasks (warp 0) -------------
    if (tid < 32) {
        const int lane = tid;
        uint32_t o0, o1;
        if (lane < 6) {
            tf2x32(0u, 42u, 0u, (uint32_t)lane, o0, o1);
            K1[2 * lane] = o0; K1[2 * lane + 1] = o1;
        }
        __syncwarp();
        if (lane < 4) {
            tf2x32(K1[0], K1[1], 0u, (uint32_t)lane, o0, o1);
            K2[2 * lane] = o0; K2[2 * lane + 1] = o1;
        } else if (lane < 7) {
            int i = lane - 4;
            tf2x32(K1[4], K1[5], 0u, (uint32_t)i, o0, o1);
            K2[8 + 2 * i] = o0; K2[9 + 2 * i] = o1;
        } else if (lane < 13) {
            int i = lane - 7;
            tf2x32(K1[8], K1[9], 0u, (uint32_t)i, o0, o1);
            K2[14 + 2 * i] = o0; K2[15 + 2 * i] = o1;
        } else if (lane < 15) {
            int i = lane - 13;
            tf2x32(K1[10], K1[11], 0u, (uint32_t)i, o0, o1);
            K2[26 + 2 * i] = o0; K2[27 + 2 * i] = o1;
        }
        __syncwarp();
        const uint32_t ub = (uint32_t)b;
        const float DEG = (float)(3.14159265358979323846 / 180.0);
        switch (lane) {
            case 0:  U[0]  = unif(rb32(K2[0],  K2[1],  ub), -25.f, 25.f) * DEG; break;
            case 1:  U[1]  = unif(rb32(K2[2],  K2[3],  ub), -15.f, 15.f) * DEG; break;
            case 2:  U[2]  = unif(rb32(K2[4],  K2[5],  ub), 0.85f, 1.15f); break;
            case 3:  U[3]  = unif(rb32(K2[6],  K2[7],  2u*ub),    -0.15f, 0.15f); break;
            case 4:  U[4]  = unif(rb32(K2[6],  K2[7],  2u*ub+1u), -0.15f, 0.15f); break;
            case 5:  U[5]  = u01f(rb32(K1[2],  K1[3],  ub)); break;
            case 6:  U[6]  = unif(rb32(K2[8],  K2[9],  ub), 0.7f, 1.3f); break;
            case 7:  U[7]  = unif(rb32(K2[10], K2[11], ub), 0.7f, 1.3f); break;
            case 8:  U[8]  = unif(rb32(K2[12], K2[13], ub), 0.8f, 1.2f); break;
            case 9:  U[9]  = u01f(rb32(K1[6],  K1[7],  ub)); break;
            case 10: U[10] = unif(rb32(K2[14], K2[15], ub), 0.02f, 0.1f); break;
            case 11: U[11] = unif(rb32(K2[16], K2[17], ub), 0.3f, 3.0f); break;
            case 12: U[12] = u01f(rb32(K2[18], K2[19], ub)); break;
            case 13: U[13] = u01f(rb32(K2[20], K2[21], ub)); break;
            case 14: U[14] = u01f(rb32(K2[24], K2[25], ub)); break;
            case 15: U[15] = floorf(unif(rb32(K2[26], K2[27], ub), 8.f, 32.f)); break;
            case 16: U[16] = u01f(rb32(K2[28], K2[29], ub)); break;
            default: break;
        }
        __syncwarp();
        if (lane == 0) {
            float ang = U[0], shr = U[1], scl = U[2];
            float c = cosf(ang), s = sinf(ang), t = tanf(shr);
            P.m00 = (c - t * (-s)) / scl;
            P.m01 = (s - t * c) / scl;
            P.m10 = (-s) / scl;
            P.m11 = c / scl;
            P.tx = U[3] * 64.0f;
            P.ty = U[4] * 64.0f;
            P.flip = (U[5] < 0.6f);
            P.br = U[6]; P.ct = U[7]; P.st = U[8];
            P.blur = (U[9] < 0.3f);
            float area = (U[10] * 64.0f) * 64.0f;
            float ratio = U[11];
            float eh = fminf(fmaxf(sqrtf(area * ratio), 1.0f), 64.0f);
            float ew = fminf(fmaxf(sqrtf(area / ratio), 1.0f), 64.0f);
            P.top = U[12] * (64.0f - eh);   P.bot = P.top + eh;
            P.left = U[13] * (64.0f - ew);  P.right = P.left + ew;
            P.eapply = (U[14] < 0.3f);
            P.gd = U[15]; P.gl = floorf(U[15] * 0.6f);
            P.gapply = (U[16] < 0.3f);
            P.kv0 = K2[22]; P.kv1 = K2[23];
        }
        __syncwarp();
        // bitmasks (warp 0 only; grid row-mask == col-mask since H==W)
        {
            float c0 = (float)lane, c1 = (float)(lane + 32);
            float gd = P.gd, gl = P.gl;
            uint32_t g0 = __ballot_sync(0xffffffffu, fmodf(c0, gd) < gl);
            uint32_t g1 = __ballot_sync(0xffffffffu, fmodf(c1, gd) < gl);
            uint32_t r0 = __ballot_sync(0xffffffffu, c0 >= P.top && c0 < P.bot);
            uint32_t r1 = __ballot_sync(0xffffffffu, c1 >= P.top && c1 < P.bot);
            uint32_t q0 = __ballot_sync(0xffffffffu, c0 >= P.left && c0 < P.right);
            uint32_t q1 = __ballot_sync(0xffffffffu, c1 >= P.left && c1 < P.right);
            if (lane == 0) {
                gm[0] = g0; gm[1] = g1;
                er_row[0] = r0; er_row[1] = r1;
                er_col[0] = q0; er_col[1] = q1;
            }
        }
    }

    // ---------------- border zeroing (one float4 store, 464 threads) --------
    if (tid < 464) {
        int addr;
        if (tid < 136) {                     // RG full border rows {0,1,66,67}
            int r = tid / 34, c4 = tid % 34;
            int row = (r < 2) ? r : 64 + r;
            addr = row * RGSTRIDE + c4 * 4;
        } else if (tid < 264) {              // RG side cols (px 0,1 / 66,67), rows 2..65
            int i = tid - 136;
            int r = 2 + (i >> 1);
            addr = r * RGSTRIDE + ((i & 1) ? 132 : 0);
        } else if (tid < 336) {              // B full border rows
            int i = tid - 264;
            int r = i / 18, c4 = i % 18;
            int row = (r < 2) ? r : 64 + r;
            addr = OFF_B + row * BSTRIDE + c4 * 4;
        } else {                             // B side cols, rows 2..65
            int i = tid - 336;
            int r = 2 + (i >> 1);
            addr = OFF_B + r * BSTRIDE + ((i & 1) ? 68 : 0);
        }
        *(float4*)(smem + addr) = make_float4(0.f, 0.f, 0.f, 0.f);
    }

    // ---------------- interior load: planar global -> RG + B planes ---------
    {
        const float4* gin4 = (const float4*)(gin + (size_t)b * CHW);
        #pragma unroll
        for (int j = 0; j < 2; j++) {
            int q = tid + j * NTHREADS;          // quad index, 4 px each
            float4 R4 = gin4[q];
            float4 G4 = gin4[q + 1024];
            float4 B4 = gin4[q + 2048];
            int h = q >> 4, w = (q & 15) << 2;
            int rgbase = ((h + 2) * 68 + (w + 2)) * 2;
            *(float4*)(sRG + rgbase)     = make_float4(R4.x, G4.x, R4.y, G4.y);
            *(float4*)(sRG + rgbase + 4) = make_float4(R4.z, G4.z, R4.w, G4.w);
            *(float4*)(sBp + (h + 2) * BSTRIDE + (w + 4)) = B4;
        }
    }
    __syncthreads();

    // ---------------- phase 1: affine warp + hflip -> sW; accumulate sum ----
    const float m00 = P.m00, m01 = P.m01, m10 = P.m10, m11 = P.m11;
    {
        const int w = tid & 63;
        const int h0 = tid >> 6;     // 0..7
        const int wd = P.flip ? (63 - w) : w;
        const float gx = (float)w - 31.5f;
        float sx = m00 * gx + m01 * ((float)h0 - 31.5f) - P.tx + 31.5f;
        float sy = m10 * gx + m11 * ((float)h0 - 31.5f) - P.ty + 31.5f;
        const float dx8 = 8.0f * m01, dy8 = 8.0f * m11;
        float lsum = 0.f;
        #pragma unroll
        for (int k = 0; k < 8; k++) {
            const int h = h0 + k * 8;
            float x0f = floorf(sx), y0f = floorf(sy);
            float wx = sx - x0f, wy = sy - y0f;
            int xi = min(max((int)x0f, -2), 64);
            int yi = min(max((int)y0f, -2), 64);
            const float* pRG = sRG + ((yi + 2) * 68 + (xi + 2)) * 2;
            const float* pB  = sBp + (yi + 2) * BSTRIDE + (xi + 4);
            float2 t00 = *(const float2*)(pRG);
            float2 t01 = *(const float2*)(pRG + 2);
            float2 t10 = *(const float2*)(pRG + RGSTRIDE);
            float2 t11 = *(const float2*)(pRG + RGSTRIDE + 2);
            float b00 = pB[0], b01 = pB[1], b10 = pB[BSTRIDE], b11 = pB[BSTRIDE + 1];
            float w11 = wx * wy;
            float w01 = wx - w11;
            float w10 = wy - w11;
            float w00 = 1.0f - wx - wy + w11;
            float vr = t00.x * w00 + t01.x * w01 + t10.x * w10 + t11.x * w11;
            float vg = t00.y * w00 + t01.y * w01 + t10.y * w10 + t11.y * w11;
            float vb = b00  * w00 + b01  * w01 + b10  * w10 + b11  * w11;
            const int sbo = h * 64 + wd;
            sW[sbo]            = vr;
            sW[HWpx + sbo]     = vg;
            sW[2 * HWpx + sbo] = vb;
            lsum += vr + vg + vb;
            sx += dx8; sy += dy8;
        }
        #pragma unroll
        for (int off = 16; off > 0; off >>= 1)
            lsum += __shfl_xor_sync(0xffffffffu, lsum, off);
        if ((tid & 31) == 0) red[tid >> 5] = lsum;
    }
    __syncthreads();

    // ---------------- optional horizontal blur pass (sW -> hA) --------------
    const bool doblur = P.blur;
    float* hA = sRG;   // reuse staging space (14144 floats >= 12288)
    if (doblur) {
        #pragma unroll
        for (int p = tid; p < HWpx; p += NTHREADS) {
            int w = p & 63;
            #pragma unroll
            for (int c = 0; c < 3; c++) {
                int i = c * HWpx + p;
                float l = (w > 0)  ? sW[i - 1] : 0.f;
                float r = (w < 63) ? sW[i + 1] : 0.f;
                hA[i] = 0.5f * sW[i] + 0.25f * (l + r);
            }
        }
        __syncthreads();
    }

    // ---- final: per-warp mean finish + vblur + jitter + masks + clamp ------
    float alpha, beta, delta;
    {
        const int lane = tid & 31;
        float t = (lane < 16) ? red[lane] : 0.f;
        #pragma unroll
        for (int off = 16; off > 0; off >>= 1)
            t += __shfl_xor_sync(0xffffffffu, t, off);
        float mean = (P.br * t) * (1.0f / 12288.0f);
        float bc = P.br * P.ct;
        alpha = P.st * bc;
        beta  = (1.0f - P.st) * bc;
        delta = mean * (1.0f - P.ct);
    }
    const bool eap = P.eapply, gap = P.gapply;
    const uint32_t kv0 = P.kv0, kv1 = P.kv1;
    float* o = gout + (size_t)b * CHW;

    #pragma unroll
    for (int j = 0; j < 2; j++) {
        const int base = (tid + j * NTHREADS) << 2;   // 4 consecutive px, same row
        const int h = base >> 6;
        const int wb = base & 63;
        const bool ghit_h = gap && ((gm[h >> 5] >> (h & 31)) & 1u);
        const bool ehit_h = eap && ((er_row[h >> 5] >> (h & 31)) & 1u);
        float vr[4], vg[4], vb[4], Sv[4];
        if (!doblur) {
            float4 R  = *(const float4*)(sW + base);
            float4 G  = *(const float4*)(sW + HWpx + base);
            float4 Bv = *(const float4*)(sW + 2 * HWpx + base);
            vr[0]=R.x; vr[1]=R.y; vr[2]=R.z; vr[3]=R.w;
            vg[0]=G.x; vg[1]=G.y; vg[2]=G.z; vg[3]=G.w;
            vb[0]=Bv.x;vb[1]=Bv.y;vb[2]=Bv.z;vb[3]=Bv.w;
            Sv[0]=Sv[1]=Sv[2]=Sv[3]=1.0f;
        } else {
            const float ry = 1.0f - 0.25f * ((h == 0) + (h == 63));
            const bool hasU = (h > 0), hasD = (h < 63);
            #pragma unroll
            for (int k = 0; k < 4; k++) {
                int p = base + k;
                int w = wb + k;
                #pragma unroll
                for (int c = 0; c < 3; c++) {
                    int i = c * HWpx + p;
                    float u = hasU ? hA[i - 64] : 0.f;
                    float d = hasD ? hA[i + 64] : 0.f;
                    float v = 0.5f * hA[i] + 0.25f * (u + d);
                    if (c == 0) vr[k] = v; else if (c == 1) vg[k] = v; else vb[k] = v;
                }
                Sv[k] = ry * (1.0f - 0.25f * ((w == 0) + (w == 63)));
            }
        }
        float4 O0, O1, O2;
        float* O0p = &O0.x; float* O1p = &O1.x; float* O2p = &O2.x;
        #pragma unroll
        for (int k = 0; k < 4; k++) {
            int w = wb + k;
            float r = vr[k], g = vg[k], bl = vb[k];
            float gray = 0.299f * r + 0.587f * g + 0.114f * bl;
            float dd = delta * Sv[k];
            float v0 = alpha * r  + beta * gray + dd;
            float v1 = alpha * g  + beta * gray + dd;
            float v2 = alpha * bl + beta * gray + dd;
            if (ehit_h && ((er_col[w >> 5] >> (w & 31)) & 1u)) {
                uint32_t rbase = ((uint32_t)b * 3u) * 4096u + (uint32_t)(base + k);
                v0 = u01f(rb32(kv0, kv1, rbase));
                v1 = u01f(rb32(kv0, kv1, rbase + 4096u));
                v2 = u01f(rb32(kv0, kv1, rbase + 8192u));
            }
            if (ghit_h && ((gm[w >> 5] >> (w & 31)) & 1u)) {
                v0 = 0.f; v1 = 0.f; v2 = 0.f;
            }
            O0p[k] = fminf(fmaxf(v0, 0.f), 1.f);
            O1p[k] = fminf(fmaxf(v1, 0.f), 1.f);
            O2p[k] = fminf(fmaxf(v2, 0.f), 1.f);
        }
        *(float4*)(o + base)            = O0;
        *(float4*)(o + HWpx + base)     = O1;
        *(float4*)(o + 2 * HWpx + base) = O2;
    }
}

extern "C" void kernel_launch(void* const* d_in, const int* in_sizes, int n_in,
                              void* d_out, int out_size) {
    (void)in_sizes; (void)n_in; (void)out_size;
    const float* x = (const float*)d_in[0];
    float* out = (float*)d_out;
    const int smem_bytes = SMEM_FLOATS * (int)sizeof(float);
    cudaFuncSetAttribute(aug_kernel, cudaFuncAttributeMaxDynamicSharedMemorySize,
                         smem_bytes);
    aug_kernel<<<BATCH, NTHREADS, smem_bytes>>>(x, out);
}